// round 11
// baseline (speedup 1.0000x reference)
#include <cuda_runtime.h>
#include <cstdint>

#define BATCH 4
#define C_DIM 128
#define HW_BIG 65536
#define HW_SM 16384
#define W_BIG 256
#define K_NBR 16
#define GATHER_BLKS (HW_SM / 8)   // 2048
#define TRANS_BLKS  (HW_BIG / 32) // 2048

// Double-buffered per-batch scratches (4 x 33.5 MB).
__device__ float g_TS[2][(size_t)HW_BIG * C_DIM];
__device__ float g_TR[2][(size_t)HW_BIG * C_DIM];

// ---------------------------------------------------------------------------
// Transpose tile body: in[c][p] -> out[p][c], one 32-pixel tile per block.
// float4 both global sides, smem stride 129 (conflict-free both phases).
// ---------------------------------------------------------------------------
__device__ __forceinline__
void transpose_tile(const float* __restrict__ in, float* __restrict__ out,
                    int blk)
{
    __shared__ float tile[32][129];
    const int p0 = blk * 32;
    const int t  = threadIdx.x;

    #pragma unroll
    for (int i0 = 0; i0 < 4; i0++) {
        const int g  = t + 256 * i0;
        const int c  = g >> 3;
        const int pq = (g & 7) * 4;
        const float4 v = __ldcs(reinterpret_cast<const float4*>(
            in + (size_t)c * HW_BIG + p0 + pq));
        tile[pq + 0][c] = v.x;
        tile[pq + 1][c] = v.y;
        tile[pq + 2][c] = v.z;
        tile[pq + 3][c] = v.w;
    }
    __syncthreads();

    const int p = t >> 3;
    #pragma unroll
    for (int i0 = 0; i0 < 4; i0++) {
        const int cg = (t & 7) + 8 * i0;
        const float4 v = make_float4(tile[p][4*cg + 0], tile[p][4*cg + 1],
                                     tile[p][4*cg + 2], tile[p][4*cg + 3]);
        *reinterpret_cast<float4*>(out + (size_t)(p0 + p) * C_DIM + 4*cg) = v;
    }
}

// ---------------------------------------------------------------------------
// Score body: warp-per-pixel, 8 pixels per block.
// ---------------------------------------------------------------------------
__device__ __forceinline__
void score_body(const float* __restrict__ Q, const int* __restrict__ PosY,
                const int* __restrict__ PosX, const float* __restrict__ T,
                float* __restrict__ outM, int blk)
{
    __shared__ float Qs[8][132];
    const int t  = threadIdx.x;
    const int p0 = blk * 8;

    #pragma unroll
    for (int i = 0; i < 4; i++) {
        const int c  = (t >> 3) + 32 * i;
        const int px = t & 7;
        Qs[px][c] = __ldcs(Q + (size_t)c * HW_SM + p0 + px);
    }
    __syncthreads();

    const int warpId = t >> 5, lane = t & 31;
    const int p = p0 + warpId;
    const float4 q4 = reinterpret_cast<const float4*>(&Qs[warpId][0])[lane];

    int idx[K_NBR];
    {
        const int4* py4 = reinterpret_cast<const int4*>(PosY + (size_t)p * K_NBR);
        const int4* px4 = reinterpret_cast<const int4*>(PosX + (size_t)p * K_NBR);
        #pragma unroll
        for (int i = 0; i < 4; i++) {
            const int4 y = py4[i];
            const int4 x = px4[i];
            idx[4*i + 0] = y.x * W_BIG + x.x;
            idx[4*i + 1] = y.y * W_BIG + x.y;
            idx[4*i + 2] = y.z * W_BIG + x.z;
            idx[4*i + 3] = y.w * W_BIG + x.w;
        }
    }

    float sc[K_NBR];
    #pragma unroll
    for (int g = 0; g < 4; g++) {
        float4 kv[4];
        #pragma unroll
        for (int j = 0; j < 4; j++)
            kv[j] = reinterpret_cast<const float4*>(
                T + (size_t)idx[g*4 + j] * C_DIM)[lane];
        #pragma unroll
        for (int j = 0; j < 4; j++)
            sc[g*4 + j] = q4.x*kv[j].x + q4.y*kv[j].y
                        + q4.z*kv[j].z + q4.w*kv[j].w;
    }

    #pragma unroll
    for (int st = 16; st >= 1; st >>= 1) {
        #pragma unroll
        for (int j = 0; j < K_NBR; j++)
            sc[j] += __shfl_xor_sync(0xffffffffu, sc[j], st);
    }

    float m = sc[0];
    #pragma unroll
    for (int j = 1; j < K_NBR; j++) m = fmaxf(m, sc[j]);
    float s = 0.f;
    #pragma unroll
    for (int j = 0; j < K_NBR; j++) { sc[j] = __expf(sc[j] - m); s += sc[j]; }
    const float inv = 1.0f / s;

    if (lane < K_NBR)
        __stcs(outM + (size_t)p * K_NBR + lane, sc[lane] * inv);
}

// ---------------------------------------------------------------------------
// Value body: warp-per-pixel, weighted value gather-sum, coalesced output.
// ---------------------------------------------------------------------------
__device__ __forceinline__
void value_body(const int* __restrict__ PosY, const int* __restrict__ PosX,
                const float* __restrict__ M, const float* __restrict__ T,
                float* __restrict__ outBuf, int blk)
{
    const int t = threadIdx.x, warpId = t >> 5, lane = t & 31;
    const int p0 = blk * 8;
    const int p  = p0 + warpId;

    int idx[K_NBR];
    float w[K_NBR];
    {
        const int4*   py4 = reinterpret_cast<const int4*>(PosY + (size_t)p * K_NBR);
        const int4*   px4 = reinterpret_cast<const int4*>(PosX + (size_t)p * K_NBR);
        const float4* m4  = reinterpret_cast<const float4*>(M + (size_t)p * K_NBR);
        #pragma unroll
        for (int i = 0; i < 4; i++) {
            const int4   y  = py4[i];
            const int4   x  = px4[i];
            const float4 ww = m4[i];
            idx[4*i + 0] = y.x * W_BIG + x.x;  w[4*i + 0] = ww.x;
            idx[4*i + 1] = y.y * W_BIG + x.y;  w[4*i + 1] = ww.y;
            idx[4*i + 2] = y.z * W_BIG + x.z;  w[4*i + 2] = ww.z;
            idx[4*i + 3] = y.w * W_BIG + x.w;  w[4*i + 3] = ww.w;
        }
    }

    float4 acc = make_float4(0.f, 0.f, 0.f, 0.f);
    #pragma unroll
    for (int g = 0; g < 4; g++) {
        float4 kv[4];
        #pragma unroll
        for (int j = 0; j < 4; j++)
            kv[j] = reinterpret_cast<const float4*>(
                T + (size_t)idx[g*4 + j] * C_DIM)[lane];
        #pragma unroll
        for (int j = 0; j < 4; j++) {
            const float ww = w[g*4 + j];
            acc.x += ww * kv[j].x;
            acc.y += ww * kv[j].y;
            acc.z += ww * kv[j].z;
            acc.w += ww * kv[j].w;
        }
    }

    __shared__ float so[8][132];
    reinterpret_cast<float4*>(&so[warpId][0])[lane] = acc;
    __syncthreads();

    const int px = t & 7;
    const int c0 = t >> 3;
    #pragma unroll
    for (int r = 0; r < 4; r++) {
        const int c = c0 + 32 * r;
        __stcs(outBuf + (size_t)c * HW_SM + p0 + px, so[px][c]);
    }
}

// ---------------------------------------------------------------------------
// Combined kernels: parity-interleaved block roles so every wave carries both
// the L2-bound gather work and the DRAM-bound transpose work.
// ---------------------------------------------------------------------------
__global__ __launch_bounds__(256)
void k_trans2(const float* __restrict__ S, const float* __restrict__ R,
              float* __restrict__ TS, float* __restrict__ TR)
{
    if (blockIdx.x & 1) transpose_tile(R, TR, blockIdx.x >> 1);
    else                transpose_tile(S, TS, blockIdx.x >> 1);
}

__global__ __launch_bounds__(256)
void k_score(const float* __restrict__ Q, const int* __restrict__ PosY,
             const int* __restrict__ PosX, const float* __restrict__ T,
             float* __restrict__ outM,
             const float* __restrict__ Tin, float* __restrict__ Tout)
{
    if (gridDim.x > GATHER_BLKS) {          // combined launch
        if (blockIdx.x & 1) { transpose_tile(Tin, Tout, blockIdx.x >> 1); return; }
        score_body(Q, PosY, PosX, T, outM, blockIdx.x >> 1);
    } else {
        score_body(Q, PosY, PosX, T, outM, blockIdx.x);
    }
}

__global__ __launch_bounds__(256)
void k_value(const int* __restrict__ PosY, const int* __restrict__ PosX,
             const float* __restrict__ M, const float* __restrict__ T,
             float* __restrict__ outBuf,
             const float* __restrict__ Tin, float* __restrict__ Tout)
{
    if (gridDim.x > GATHER_BLKS) {
        if (blockIdx.x & 1) { transpose_tile(Tin, Tout, blockIdx.x >> 1); return; }
        value_body(PosY, PosX, M, T, outBuf, blockIdx.x >> 1);
    } else {
        value_body(PosY, PosX, M, T, outBuf, blockIdx.x);
    }
}

extern "C" void kernel_launch(void* const* d_in, const int* in_sizes, int n_in,
                              void* d_out, int out_size)
{
    const float* Q   = (const float*)d_in[0];
    const float* S   = (const float*)d_in[1];
    const float* R   = (const float*)d_in[2];
    const int*   Pos = (const int*)d_in[3];

    float* outBuf = (float*)d_out;                                // B*C*hw
    float* outM   = outBuf + (size_t)BATCH * C_DIM * HW_SM;       // B*hw*k

    float* TS[2]; float* TR[2];
    cudaGetSymbolAddress((void**)&TS[0], g_TS);
    cudaGetSymbolAddress((void**)&TR[0], g_TR);
    TS[1] = TS[0] + (size_t)HW_BIG * C_DIM;
    TR[1] = TR[0] + (size_t)HW_BIG * C_DIM;

    const size_t sStride = (size_t)C_DIM * HW_BIG;

    // K0: both batch-0 transposes
    k_trans2<<<2 * TRANS_BLKS, 256>>>(S, R, TS[0], TR[0]);

    for (int b = 0; b < BATCH; b++) {
        const float* Qb = Q + (size_t)b * C_DIM * HW_SM;
        const int*   PY = Pos + (size_t)b * 2 * HW_SM * K_NBR;
        const int*   PX = PY + (size_t)HW_SM * K_NBR;
        float*       Mb = outM   + (size_t)b * HW_SM * K_NBR;
        float*       Ob = outBuf + (size_t)b * C_DIM * HW_SM;
        const int cur = b & 1, nxt = (b + 1) & 1;
        const bool more = (b + 1) < BATCH;

        // score(b) reads TS[cur]; overlapped transpose S_{b+1} -> TS[nxt]
        if (more)
            k_score<<<2 * GATHER_BLKS, 256>>>(Qb, PY, PX, TS[cur], Mb,
                                              S + (size_t)(b + 1) * sStride, TS[nxt]);
        else
            k_score<<<GATHER_BLKS, 256>>>(Qb, PY, PX, TS[cur], Mb, nullptr, nullptr);

        // value(b) reads TR[cur]; overlapped transpose R_{b+1} -> TR[nxt]
        if (more)
            k_value<<<2 * GATHER_BLKS, 256>>>(PY, PX, Mb, TR[cur], Ob,
                                              R + (size_t)(b + 1) * sStride, TR[nxt]);
        else
            k_value<<<GATHER_BLKS, 256>>>(PY, PX, Mb, TR[cur], Ob, nullptr, nullptr);
    }
}

// round 12
// speedup vs baseline: 1.1404x; 1.1404x over previous
#include <cuda_runtime.h>
#include <cstdint>

#define BATCH 4
#define C_DIM 128
#define HW_BIG 65536
#define HW_SM 16384
#define W_BIG 256
#define K_NBR 16
#define GATHER_BLKS (HW_SM / 8)   // 2048
#define TRANS_BLKS  (HW_BIG / 32) // 2048
#define SH_FLOATS   (32 * 129)    // 16512 B union

// Single-buffered per-batch scratches (2 x 33.5 MB). Rotated schedule keeps
// the per-kernel L2 hot set at 67 MB (< 126 MB L2).
__device__ float g_TS[(size_t)HW_BIG * C_DIM];
__device__ float g_TR[(size_t)HW_BIG * C_DIM];

// ---------------------------------------------------------------------------
// Transpose tile body: in[c][p] -> out[p][c], one 32-pixel tile per block.
// ---------------------------------------------------------------------------
__device__ __forceinline__
void transpose_tile(const float* __restrict__ in, float* __restrict__ out,
                    int blk, float* sh)
{
    float (*tile)[129] = reinterpret_cast<float (*)[129]>(sh);
    const int p0 = blk * 32;
    const int t  = threadIdx.x;

    #pragma unroll
    for (int i0 = 0; i0 < 4; i0++) {
        const int g  = t + 256 * i0;
        const int c  = g >> 3;
        const int pq = (g & 7) * 4;
        const float4 v = __ldcs(reinterpret_cast<const float4*>(
            in + (size_t)c * HW_BIG + p0 + pq));
        tile[pq + 0][c] = v.x;
        tile[pq + 1][c] = v.y;
        tile[pq + 2][c] = v.z;
        tile[pq + 3][c] = v.w;
    }
    __syncthreads();

    const int p = t >> 3;
    #pragma unroll
    for (int i0 = 0; i0 < 4; i0++) {
        const int cg = (t & 7) + 8 * i0;
        const float4 v = make_float4(tile[p][4*cg + 0], tile[p][4*cg + 1],
                                     tile[p][4*cg + 2], tile[p][4*cg + 3]);
        *reinterpret_cast<float4*>(out + (size_t)(p0 + p) * C_DIM + 4*cg) = v;
    }
}

// ---------------------------------------------------------------------------
// Score body: warp-per-pixel, 8 pixels per block.
// ---------------------------------------------------------------------------
__device__ __forceinline__
void score_body(const float* __restrict__ Q, const int* __restrict__ PosY,
                const int* __restrict__ PosX, const float* __restrict__ T,
                float* __restrict__ outM, int blk, float* sh)
{
    float (*Qs)[132] = reinterpret_cast<float (*)[132]>(sh);
    const int t  = threadIdx.x;
    const int p0 = blk * 8;

    #pragma unroll
    for (int i = 0; i < 4; i++) {
        const int c  = (t >> 3) + 32 * i;
        const int px = t & 7;
        Qs[px][c] = __ldcs(Q + (size_t)c * HW_SM + p0 + px);
    }
    __syncthreads();

    const int warpId = t >> 5, lane = t & 31;
    const int p = p0 + warpId;
    const float4 q4 = reinterpret_cast<const float4*>(&Qs[warpId][0])[lane];

    int idx[K_NBR];
    {
        const int4* py4 = reinterpret_cast<const int4*>(PosY + (size_t)p * K_NBR);
        const int4* px4 = reinterpret_cast<const int4*>(PosX + (size_t)p * K_NBR);
        #pragma unroll
        for (int i = 0; i < 4; i++) {
            const int4 y = py4[i];
            const int4 x = px4[i];
            idx[4*i + 0] = y.x * W_BIG + x.x;
            idx[4*i + 1] = y.y * W_BIG + x.y;
            idx[4*i + 2] = y.z * W_BIG + x.z;
            idx[4*i + 3] = y.w * W_BIG + x.w;
        }
    }

    float sc[K_NBR];
    #pragma unroll
    for (int g = 0; g < 4; g++) {
        float4 kv[4];
        #pragma unroll
        for (int j = 0; j < 4; j++)
            kv[j] = reinterpret_cast<const float4*>(
                T + (size_t)idx[g*4 + j] * C_DIM)[lane];
        #pragma unroll
        for (int j = 0; j < 4; j++)
            sc[g*4 + j] = q4.x*kv[j].x + q4.y*kv[j].y
                        + q4.z*kv[j].z + q4.w*kv[j].w;
    }

    #pragma unroll
    for (int st = 16; st >= 1; st >>= 1) {
        #pragma unroll
        for (int j = 0; j < K_NBR; j++)
            sc[j] += __shfl_xor_sync(0xffffffffu, sc[j], st);
    }

    float m = sc[0];
    #pragma unroll
    for (int j = 1; j < K_NBR; j++) m = fmaxf(m, sc[j]);
    float s = 0.f;
    #pragma unroll
    for (int j = 0; j < K_NBR; j++) { sc[j] = __expf(sc[j] - m); s += sc[j]; }
    const float inv = 1.0f / s;

    if (lane < K_NBR)
        __stcs(outM + (size_t)p * K_NBR + lane, sc[lane] * inv);
}

// ---------------------------------------------------------------------------
// Value body: warp-per-pixel, weighted value gather-sum, coalesced output.
// ---------------------------------------------------------------------------
__device__ __forceinline__
void value_body(const int* __restrict__ PosY, const int* __restrict__ PosX,
                const float* __restrict__ M, const float* __restrict__ T,
                float* __restrict__ outBuf, int blk, float* sh)
{
    const int t = threadIdx.x, warpId = t >> 5, lane = t & 31;
    const int p0 = blk * 8;
    const int p  = p0 + warpId;

    int idx[K_NBR];
    float w[K_NBR];
    {
        const int4*   py4 = reinterpret_cast<const int4*>(PosY + (size_t)p * K_NBR);
        const int4*   px4 = reinterpret_cast<const int4*>(PosX + (size_t)p * K_NBR);
        const float4* m4  = reinterpret_cast<const float4*>(M + (size_t)p * K_NBR);
        #pragma unroll
        for (int i = 0; i < 4; i++) {
            const int4   y  = py4[i];
            const int4   x  = px4[i];
            const float4 ww = m4[i];
            idx[4*i + 0] = y.x * W_BIG + x.x;  w[4*i + 0] = ww.x;
            idx[4*i + 1] = y.y * W_BIG + x.y;  w[4*i + 1] = ww.y;
            idx[4*i + 2] = y.z * W_BIG + x.z;  w[4*i + 2] = ww.z;
            idx[4*i + 3] = y.w * W_BIG + x.w;  w[4*i + 3] = ww.w;
        }
    }

    float4 acc = make_float4(0.f, 0.f, 0.f, 0.f);
    #pragma unroll
    for (int g = 0; g < 4; g++) {
        float4 kv[4];
        #pragma unroll
        for (int j = 0; j < 4; j++)
            kv[j] = reinterpret_cast<const float4*>(
                T + (size_t)idx[g*4 + j] * C_DIM)[lane];
        #pragma unroll
        for (int j = 0; j < 4; j++) {
            const float ww = w[g*4 + j];
            acc.x += ww * kv[j].x;
            acc.y += ww * kv[j].y;
            acc.z += ww * kv[j].z;
            acc.w += ww * kv[j].w;
        }
    }

    float (*so)[132] = reinterpret_cast<float (*)[132]>(sh);
    reinterpret_cast<float4*>(&so[warpId][0])[lane] = acc;
    __syncthreads();

    const int px = t & 7;
    const int c0 = t >> 3;
    #pragma unroll
    for (int r = 0; r < 4; r++) {
        const int c = c0 + 32 * r;
        __stcs(outBuf + (size_t)c * HW_SM + p0 + px, so[px][c]);
    }
}

// ---------------------------------------------------------------------------
// Kernels. Combined launches (grid = 4096) interleave gather blocks (even)
// with transpose blocks (odd); pure launches (grid = 2048) do gather only.
// One 16.5 KB smem union serves all roles.
// ---------------------------------------------------------------------------
__global__ __launch_bounds__(256)
void k_trans(const float* __restrict__ in, float* __restrict__ out)
{
    __shared__ float sh[SH_FLOATS];
    transpose_tile(in, out, blockIdx.x, sh);
}

__global__ __launch_bounds__(256)
void k_score(const float* __restrict__ Q, const int* __restrict__ PosY,
             const int* __restrict__ PosX, const float* __restrict__ T,
             float* __restrict__ outM,
             const float* __restrict__ Tin, float* __restrict__ Tout)
{
    __shared__ float sh[SH_FLOATS];
    if (gridDim.x > GATHER_BLKS) {
        if (blockIdx.x & 1) { transpose_tile(Tin, Tout, blockIdx.x >> 1, sh); return; }
        score_body(Q, PosY, PosX, T, outM, blockIdx.x >> 1, sh);
    } else {
        score_body(Q, PosY, PosX, T, outM, blockIdx.x, sh);
    }
}

__global__ __launch_bounds__(256)
void k_value(const int* __restrict__ PosY, const int* __restrict__ PosX,
             const float* __restrict__ M, const float* __restrict__ T,
             float* __restrict__ outBuf,
             const float* __restrict__ Tin, float* __restrict__ Tout)
{
    __shared__ float sh[SH_FLOATS];
    if (gridDim.x > GATHER_BLKS) {
        if (blockIdx.x & 1) { transpose_tile(Tin, Tout, blockIdx.x >> 1, sh); return; }
        value_body(PosY, PosX, M, T, outBuf, blockIdx.x >> 1, sh);
    } else {
        value_body(PosY, PosX, M, T, outBuf, blockIdx.x, sh);
    }
}

extern "C" void kernel_launch(void* const* d_in, const int* in_sizes, int n_in,
                              void* d_out, int out_size)
{
    const float* Q   = (const float*)d_in[0];
    const float* S   = (const float*)d_in[1];
    const float* R   = (const float*)d_in[2];
    const int*   Pos = (const int*)d_in[3];

    float* outBuf = (float*)d_out;                                // B*C*hw
    float* outM   = outBuf + (size_t)BATCH * C_DIM * HW_SM;       // B*hw*k

    float* TS; float* TR;
    cudaGetSymbolAddress((void**)&TS, g_TS);
    cudaGetSymbolAddress((void**)&TR, g_TR);

    const size_t sStride = (size_t)C_DIM * HW_BIG;

    // Lead-in: transpose S0 -> TS
    k_trans<<<TRANS_BLKS, 256>>>(S, TS);

    // Rotated single-buffer schedule (hazard-free):
    //   score_b reads TS  while transposing R_b   -> TR
    //   value_b reads TR  while transposing S_{b+1} -> TS
    for (int b = 0; b < BATCH; b++) {
        const float* Qb = Q + (size_t)b * C_DIM * HW_SM;
        const int*   PY = Pos + (size_t)b * 2 * HW_SM * K_NBR;
        const int*   PX = PY + (size_t)HW_SM * K_NBR;
        float*       Mb = outM   + (size_t)b * HW_SM * K_NBR;
        float*       Ob = outBuf + (size_t)b * C_DIM * HW_SM;

        // score(b) + transpose R_b -> TR
        k_score<<<2 * GATHER_BLKS, 256>>>(Qb, PY, PX, TS, Mb,
                                          R + (size_t)b * sStride, TR);

        // value(b) + transpose S_{b+1} -> TS (skip on last batch)
        if (b + 1 < BATCH)
            k_value<<<2 * GATHER_BLKS, 256>>>(PY, PX, Mb, TR, Ob,
                                              S + (size_t)(b + 1) * sStride, TS);
        else
            k_value<<<GATHER_BLKS, 256>>>(PY, PX, Mb, TR, Ob, nullptr, nullptr);
    }
}

// round 14
// speedup vs baseline: 1.1991x; 1.0515x over previous
#include <cuda_runtime.h>
#include <cuda_fp16.h>
#include <cstdint>

#define BATCH 4
#define C_DIM 128
#define HW_BIG 65536
#define HW_SM 16384
#define W_BIG 256
#define K_NBR 16

// Per-batch scratches, single-buffered, reused across batches at the same
// addresses. Keys fp32 (33.5MB) + values fp16 (16.8MB) = 50MB -> L2-resident.
__device__ float  g_TS[(size_t)HW_BIG * C_DIM];
__device__ __half g_TR[(size_t)HW_BIG * C_DIM];

// ---------------------------------------------------------------------------
// Transpose S (fp32 -> fp32 pixel-major): in[c][p] -> out[p][c]
// ---------------------------------------------------------------------------
__global__ __launch_bounds__(256)
void k_transS(const float* __restrict__ in, float* __restrict__ out)
{
    __shared__ float tile[32][129];
    const int p0 = blockIdx.x * 32;
    const int t  = threadIdx.x;

    #pragma unroll
    for (int i0 = 0; i0 < 4; i0++) {
        const int g  = t + 256 * i0;
        const int c  = g >> 3;
        const int pq = (g & 7) * 4;
        const float4 v = __ldcs(reinterpret_cast<const float4*>(
            in + (size_t)c * HW_BIG + p0 + pq));
        tile[pq + 0][c] = v.x;
        tile[pq + 1][c] = v.y;
        tile[pq + 2][c] = v.z;
        tile[pq + 3][c] = v.w;
    }
    __syncthreads();

    const int p = t >> 3;
    #pragma unroll
    for (int i0 = 0; i0 < 4; i0++) {
        const int cg = (t & 7) + 8 * i0;
        const float4 v = make_float4(tile[p][4*cg + 0], tile[p][4*cg + 1],
                                     tile[p][4*cg + 2], tile[p][4*cg + 3]);
        *reinterpret_cast<float4*>(out + (size_t)(p0 + p) * C_DIM + 4*cg) = v;
    }
}

// ---------------------------------------------------------------------------
// Transpose R (fp32 -> fp16 pixel-major): in[c][p] -> out[p][c] as __half
// ---------------------------------------------------------------------------
__global__ __launch_bounds__(256)
void k_transR(const float* __restrict__ in, __half* __restrict__ out)
{
    __shared__ float tile[32][129];
    const int p0 = blockIdx.x * 32;
    const int t  = threadIdx.x;

    #pragma unroll
    for (int i0 = 0; i0 < 4; i0++) {
        const int g  = t + 256 * i0;
        const int c  = g >> 3;
        const int pq = (g & 7) * 4;
        const float4 v = __ldcs(reinterpret_cast<const float4*>(
            in + (size_t)c * HW_BIG + p0 + pq));
        tile[pq + 0][c] = v.x;
        tile[pq + 1][c] = v.y;
        tile[pq + 2][c] = v.z;
        tile[pq + 3][c] = v.w;
    }
    __syncthreads();

    const int p = t >> 3;
    #pragma unroll
    for (int i0 = 0; i0 < 4; i0++) {
        const int cg = (t & 7) + 8 * i0;
        const __half2 h0 = __floats2half2_rn(tile[p][4*cg + 0], tile[p][4*cg + 1]);
        const __half2 h1 = __floats2half2_rn(tile[p][4*cg + 2], tile[p][4*cg + 3]);
        uint2 u;
        u.x = *reinterpret_cast<const unsigned int*>(&h0);
        u.y = *reinterpret_cast<const unsigned int*>(&h1);
        *reinterpret_cast<uint2*>(out + (size_t)(p0 + p) * C_DIM + 4*cg) = u;
    }
}

// ---------------------------------------------------------------------------
// Fused attention: score gather (fp32 keys) + softmax + value gather (fp16
// values), warp-per-pixel, gathers issued in groups of 8 for MLP.
// ---------------------------------------------------------------------------
__global__ __launch_bounds__(256)
void attn_fused_kernel(const float* __restrict__ Q,     // batch: C x HW_SM
                       const int*   __restrict__ PosY,
                       const int*   __restrict__ PosX,
                       float*       __restrict__ outM,  // batch: HW_SM * K
                       float*       __restrict__ outBuf)// batch: C x HW_SM
{
    __shared__ float stage[8][132];
    const int t  = threadIdx.x;
    const int p0 = blockIdx.x * 8;

    #pragma unroll
    for (int i = 0; i < 4; i++) {
        const int c  = (t >> 3) + 32 * i;
        const int px = t & 7;
        stage[px][c] = __ldcs(Q + (size_t)c * HW_SM + p0 + px);
    }
    __syncthreads();

    const int warpId = t >> 5, lane = t & 31;
    const int p = p0 + warpId;

    const float4 q4 = reinterpret_cast<const float4*>(&stage[warpId][0])[lane];
    __syncthreads();   // stage reused for output

    int idx[K_NBR];
    {
        const int4* py4 = reinterpret_cast<const int4*>(PosY + (size_t)p * K_NBR);
        const int4* px4 = reinterpret_cast<const int4*>(PosX + (size_t)p * K_NBR);
        #pragma unroll
        for (int i = 0; i < 4; i++) {
            const int4 y = py4[i];
            const int4 x = px4[i];
            idx[4*i + 0] = y.x * W_BIG + x.x;
            idx[4*i + 1] = y.y * W_BIG + x.y;
            idx[4*i + 2] = y.z * W_BIG + x.z;
            idx[4*i + 3] = y.w * W_BIG + x.w;
        }
    }

    // ---- score gathers (fp32 keys), groups of 8 in flight ----
    float sc[K_NBR];
    #pragma unroll
    for (int g = 0; g < 2; g++) {
        float4 kv[8];
        #pragma unroll
        for (int j = 0; j < 8; j++)
            kv[j] = reinterpret_cast<const float4*>(
                g_TS + (size_t)idx[g*8 + j] * C_DIM)[lane];
        #pragma unroll
        for (int j = 0; j < 8; j++)
            sc[g*8 + j] = q4.x*kv[j].x + q4.y*kv[j].y
                        + q4.z*kv[j].z + q4.w*kv[j].w;
    }

    #pragma unroll
    for (int st = 16; st >= 1; st >>= 1) {
        #pragma unroll
        for (int j = 0; j < K_NBR; j++)
            sc[j] += __shfl_xor_sync(0xffffffffu, sc[j], st);
    }

    // ---- softmax ----
    float m = sc[0];
    #pragma unroll
    for (int j = 1; j < K_NBR; j++) m = fmaxf(m, sc[j]);
    float s = 0.f;
    #pragma unroll
    for (int j = 0; j < K_NBR; j++) { sc[j] = __expf(sc[j] - m); s += sc[j]; }
    const float inv = 1.0f / s;
    #pragma unroll
    for (int j = 0; j < K_NBR; j++) sc[j] *= inv;

    if (lane < K_NBR)
        __stcs(outM + (size_t)p * K_NBR + lane, sc[lane]);

    // ---- value gathers (fp16 values), groups of 8 in flight ----
    // Lane covers channels 4*lane..4*lane+3 (uint2 = 4 halves), matching q4.
    float4 acc = make_float4(0.f, 0.f, 0.f, 0.f);
    #pragma unroll
    for (int g = 0; g < 2; g++) {
        uint2 kv[8];
        #pragma unroll
        for (int j = 0; j < 8; j++)
            kv[j] = reinterpret_cast<const uint2*>(
                g_TR + (size_t)idx[g*8 + j] * C_DIM)[lane];
        #pragma unroll
        for (int j = 0; j < 8; j++) {
            const float w = sc[g*8 + j];
            const __half2 h0 = *reinterpret_cast<const __half2*>(&kv[j].x);
            const __half2 h1 = *reinterpret_cast<const __half2*>(&kv[j].y);
            const float2 f0 = __half22float2(h0);
            const float2 f1 = __half22float2(h1);
            acc.x += w * f0.x;
            acc.y += w * f0.y;
            acc.z += w * f1.x;
            acc.w += w * f1.y;
        }
    }

    // ---- coalesced channel-major buffer store via smem ----
    reinterpret_cast<float4*>(&stage[warpId][0])[lane] = acc;
    __syncthreads();

    const int px = t & 7;
    const int c0 = t >> 3;
    #pragma unroll
    for (int r = 0; r < 4; r++) {
        const int c = c0 + 32 * r;
        __stcs(outBuf + (size_t)c * HW_SM + p0 + px, stage[px][c]);
    }
}

extern "C" void kernel_launch(void* const* d_in, const int* in_sizes, int n_in,
                              void* d_out, int out_size)
{
    const float* Q   = (const float*)d_in[0];
    const float* S   = (const float*)d_in[1];
    const float* R   = (const float*)d_in[2];
    const int*   Pos = (const int*)d_in[3];

    float* outBuf = (float*)d_out;                                // B*C*hw
    float* outM   = outBuf + (size_t)BATCH * C_DIM * HW_SM;       // B*hw*k

    float*  TS; cudaGetSymbolAddress((void**)&TS, g_TS);
    __half* TR; cudaGetSymbolAddress((void**)&TR, g_TR);

    for (int b = 0; b < BATCH; b++) {
        const float* Sb = S + (size_t)b * C_DIM * HW_BIG;
        const float* Rb = R + (size_t)b * C_DIM * HW_BIG;
        const float* Qb = Q + (size_t)b * C_DIM * HW_SM;
        const int*   PY = Pos + (size_t)b * 2 * HW_SM * K_NBR;
        const int*   PX = PY + (size_t)HW_SM * K_NBR;
        float*       Mb = outM   + (size_t)b * HW_SM * K_NBR;
        float*       Ob = outBuf + (size_t)b * C_DIM * HW_SM;

        k_transS<<<HW_BIG / 32, 256>>>(Sb, TS);
        k_transR<<<HW_BIG / 32, 256>>>(Rb, TR);
        attn_fused_kernel<<<HW_SM / 8, 256>>>(Qb, PY, PX, Mb, Ob);
    }
}

// round 15
// speedup vs baseline: 1.2693x; 1.0586x over previous
#include <cuda_runtime.h>
#include <cuda_fp16.h>
#include <cstdint>

#define BATCH 4
#define C_DIM 128
#define HW_BIG 65536
#define HW_SM 16384
#define W_BIG 256
#define K_NBR 16
#define TRANS_BLKS (HW_BIG / 32)   // 2048 tiles per array

// Per-batch scratches, single-buffered, reused across batches at the same
// addresses. Keys fp32 (33.5MB) + values fp16 (16.8MB) = 50MB -> L2-resident.
__device__ float  g_TS[(size_t)HW_BIG * C_DIM];
__device__ __half g_TR[(size_t)HW_BIG * C_DIM];

// ---------------------------------------------------------------------------
// Combined transpose: one launch per batch moves BOTH arrays so the two
// latency-bound streams stack and saturate the chip LTS cap.
//   blocks [0, 2048)    : S tile -> g_TS (fp32)
//   blocks [2048, 4096) : R tile -> g_TR (fp16)
// ---------------------------------------------------------------------------
__global__ __launch_bounds__(256)
void k_trans2(const float* __restrict__ S, const float* __restrict__ R)
{
    __shared__ float tile[32][129];
    const bool isR = blockIdx.x >= TRANS_BLKS;
    const int  blk = isR ? (blockIdx.x - TRANS_BLKS) : blockIdx.x;
    const float* in = isR ? R : S;

    const int p0 = blk * 32;
    const int t  = threadIdx.x;

    #pragma unroll
    for (int i0 = 0; i0 < 4; i0++) {
        const int g  = t + 256 * i0;
        const int c  = g >> 3;
        const int pq = (g & 7) * 4;
        const float4 v = __ldcs(reinterpret_cast<const float4*>(
            in + (size_t)c * HW_BIG + p0 + pq));
        tile[pq + 0][c] = v.x;
        tile[pq + 1][c] = v.y;
        tile[pq + 2][c] = v.z;
        tile[pq + 3][c] = v.w;
    }
    __syncthreads();

    const int p = t >> 3;
    if (!isR) {
        #pragma unroll
        for (int i0 = 0; i0 < 4; i0++) {
            const int cg = (t & 7) + 8 * i0;
            const float4 v = make_float4(tile[p][4*cg + 0], tile[p][4*cg + 1],
                                         tile[p][4*cg + 2], tile[p][4*cg + 3]);
            *reinterpret_cast<float4*>(g_TS + (size_t)(p0 + p) * C_DIM + 4*cg) = v;
        }
    } else {
        #pragma unroll
        for (int i0 = 0; i0 < 4; i0++) {
            const int cg = (t & 7) + 8 * i0;
            const __half2 h0 = __floats2half2_rn(tile[p][4*cg + 0], tile[p][4*cg + 1]);
            const __half2 h1 = __floats2half2_rn(tile[p][4*cg + 2], tile[p][4*cg + 3]);
            uint2 u;
            u.x = *reinterpret_cast<const unsigned int*>(&h0);
            u.y = *reinterpret_cast<const unsigned int*>(&h1);
            *reinterpret_cast<uint2*>(g_TR + (size_t)(p0 + p) * C_DIM + 4*cg) = u;
        }
    }
}

// ---------------------------------------------------------------------------
// Fused attention: score gather (fp32 keys) + softmax + value gather (fp16
// values), warp-per-pixel, gathers issued in groups of 8 for MLP.
// ---------------------------------------------------------------------------
__global__ __launch_bounds__(256)
void attn_fused_kernel(const float* __restrict__ Q,     // batch: C x HW_SM
                       const int*   __restrict__ PosY,
                       const int*   __restrict__ PosX,
                       float*       __restrict__ outM,  // batch: HW_SM * K
                       float*       __restrict__ outBuf)// batch: C x HW_SM
{
    __shared__ float stage[8][132];
    const int t  = threadIdx.x;
    const int p0 = blockIdx.x * 8;

    #pragma unroll
    for (int i = 0; i < 4; i++) {
        const int c  = (t >> 3) + 32 * i;
        const int px = t & 7;
        stage[px][c] = __ldcs(Q + (size_t)c * HW_SM + p0 + px);
    }
    __syncthreads();

    const int warpId = t >> 5, lane = t & 31;
    const int p = p0 + warpId;

    const float4 q4 = reinterpret_cast<const float4*>(&stage[warpId][0])[lane];
    __syncthreads();   // stage reused for output

    int idx[K_NBR];
    {
        const int4* py4 = reinterpret_cast<const int4*>(PosY + (size_t)p * K_NBR);
        const int4* px4 = reinterpret_cast<const int4*>(PosX + (size_t)p * K_NBR);
        #pragma unroll
        for (int i = 0; i < 4; i++) {
            const int4 y = py4[i];
            const int4 x = px4[i];
            idx[4*i + 0] = y.x * W_BIG + x.x;
            idx[4*i + 1] = y.y * W_BIG + x.y;
            idx[4*i + 2] = y.z * W_BIG + x.z;
            idx[4*i + 3] = y.w * W_BIG + x.w;
        }
    }

    // ---- score gathers (fp32 keys), groups of 8 in flight ----
    float sc[K_NBR];
    #pragma unroll
    for (int g = 0; g < 2; g++) {
        float4 kv[8];
        #pragma unroll
        for (int j = 0; j < 8; j++)
            kv[j] = reinterpret_cast<const float4*>(
                g_TS + (size_t)idx[g*8 + j] * C_DIM)[lane];
        #pragma unroll
        for (int j = 0; j < 8; j++)
            sc[g*8 + j] = q4.x*kv[j].x + q4.y*kv[j].y
                        + q4.z*kv[j].z + q4.w*kv[j].w;
    }

    #pragma unroll
    for (int st = 16; st >= 1; st >>= 1) {
        #pragma unroll
        for (int j = 0; j < K_NBR; j++)
            sc[j] += __shfl_xor_sync(0xffffffffu, sc[j], st);
    }

    // ---- softmax ----
    float m = sc[0];
    #pragma unroll
    for (int j = 1; j < K_NBR; j++) m = fmaxf(m, sc[j]);
    float s = 0.f;
    #pragma unroll
    for (int j = 0; j < K_NBR; j++) { sc[j] = __expf(sc[j] - m); s += sc[j]; }
    const float inv = 1.0f / s;
    #pragma unroll
    for (int j = 0; j < K_NBR; j++) sc[j] *= inv;

    if (lane < K_NBR)
        __stcs(outM + (size_t)p * K_NBR + lane, sc[lane]);

    // ---- value gathers (fp16 values), groups of 8 in flight ----
    float4 acc = make_float4(0.f, 0.f, 0.f, 0.f);
    #pragma unroll
    for (int g = 0; g < 2; g++) {
        uint2 kv[8];
        #pragma unroll
        for (int j = 0; j < 8; j++)
            kv[j] = reinterpret_cast<const uint2*>(
                g_TR + (size_t)idx[g*8 + j] * C_DIM)[lane];
        #pragma unroll
        for (int j = 0; j < 8; j++) {
            const float w = sc[g*8 + j];
            const __half2 h0 = *reinterpret_cast<const __half2*>(&kv[j].x);
            const __half2 h1 = *reinterpret_cast<const __half2*>(&kv[j].y);
            const float2 f0 = __half22float2(h0);
            const float2 f1 = __half22float2(h1);
            acc.x += w * f0.x;
            acc.y += w * f0.y;
            acc.z += w * f1.x;
            acc.w += w * f1.y;
        }
    }

    // ---- coalesced channel-major buffer store via smem ----
    reinterpret_cast<float4*>(&stage[warpId][0])[lane] = acc;
    __syncthreads();

    const int px = t & 7;
    const int c0 = t >> 3;
    #pragma unroll
    for (int r = 0; r < 4; r++) {
        const int c = c0 + 32 * r;
        __stcs(outBuf + (size_t)c * HW_SM + p0 + px, stage[px][c]);
    }
}

extern "C" void kernel_launch(void* const* d_in, const int* in_sizes, int n_in,
                              void* d_out, int out_size)
{
    const float* Q   = (const float*)d_in[0];
    const float* S   = (const float*)d_in[1];
    const float* R   = (const float*)d_in[2];
    const int*   Pos = (const int*)d_in[3];

    float* outBuf = (float*)d_out;                                // B*C*hw
    float* outM   = outBuf + (size_t)BATCH * C_DIM * HW_SM;       // B*hw*k

    for (int b = 0; b < BATCH; b++) {
        const float* Sb = S + (size_t)b * C_DIM * HW_BIG;
        const float* Rb = R + (size_t)b * C_DIM * HW_BIG;
        const float* Qb = Q + (size_t)b * C_DIM * HW_SM;
        const int*   PY = Pos + (size_t)b * 2 * HW_SM * K_NBR;
        const int*   PX = PY + (size_t)HW_SM * K_NBR;
        float*       Mb = outM   + (size_t)b * HW_SM * K_NBR;
        float*       Ob = outBuf + (size_t)b * C_DIM * HW_SM;

        k_trans2<<<2 * TRANS_BLKS, 256>>>(Sb, Rb);
        attn_fused_kernel<<<HW_SM / 8, 256>>>(Qb, PY, PX, Mb, Ob);
    }
}